// round 16
// baseline (speedup 1.0000x reference)
#include <cuda_runtime.h>
#include <cuda_fp16.h>
#include <cstdint>

// Problem constants
#define NHEAD   8
#define DK      64
#define LEN     100
#define BS      32
#define DMODEL  512
#define TEMP    20.0f
#define LN8192  9.0109133f
#define RSCALE  32.0f          // residual scale for 2-mma exact-ish S
#define RINV    0.03125f       // 1/32

// Q: FRAGMENT-ORDER image per (b,h): word idx = (fs*4+ks)*128 + lane*4+u,
//    fs = row/16 (0..7). Unwritten words (rows>=100) stay zero (static init).
__device__ __align__(16) uint32_t g_Qh[BS * NHEAD * 4096];
__device__ __align__(16) uint32_t g_Qx[BS * NHEAD * 4096];
// K: FRAGMENT-ORDER B image per (b,h): word idx = (j*4+ks)*64 + lane*2 + u,
//    j = col/8 (0..13). Cols >= 100 stay zero.
__device__ __align__(16) uint32_t g_Kh[BS * NHEAD * 3584];
__device__ __align__(16) uint32_t g_Kx[BS * NHEAD * 3584];
// V: FRAGMENT-ORDER image per (kb,h): word idx = ((jv*7)+ks)*64 + lane*2 + u.
__device__ __align__(16) uint32_t g_Vf[BS * NHEAD * 3584];

// ---------------------------------------------------------------------------
__device__ __forceinline__ void mma_f16(float c[4],
    uint32_t a0, uint32_t a1, uint32_t a2, uint32_t a3,
    uint32_t b0, uint32_t b1)
{
    asm volatile(
        "mma.sync.aligned.m16n8k16.row.col.f32.f16.f16.f32 "
        "{%0,%1,%2,%3}, {%4,%5,%6,%7}, {%8,%9}, {%0,%1,%2,%3};"
        : "+f"(c[0]), "+f"(c[1]), "+f"(c[2]), "+f"(c[3])
        : "r"(a0), "r"(a1), "r"(a2), "r"(a3), "r"(b0), "r"(b1));
}

__device__ __forceinline__ void split2h(float x0, float x1,
                                        uint32_t& hi, uint32_t& lo)
{
    __half2 h = __floats2half2_rn(x0, x1);
    float2 hf = __half22float2(h);
    __half2 l = __floats2half2_rn(x0 - hf.x, x1 - hf.y);
    hi = *(uint32_t*)&h;
    lo = *(uint32_t*)&l;
}

// h = fp16(y), x = fp16(h + 32*(y-h))  (scaled-residual pair)
__device__ __forceinline__ void splitrx(float y0, float y1,
                                        uint32_t& hw, uint32_t& xw)
{
    __half2 h = __floats2half2_rn(y0, y1);
    float2 hf = __half22float2(h);
    __half2 x = __floats2half2_rn(fmaf(RSCALE, y0 - hf.x, hf.x),
                                  fmaf(RSCALE, y1 - hf.y, hf.y));
    hw = *(uint32_t*)&h;
    xw = *(uint32_t*)&x;
}

// ---------------------------------------------------------------------------
// Kernel 1: projection (z=0: Q frag-order; z=1: K frag-order B image) +
//           z=2 slice: V^T frag-order image builder. (unchanged from r15)
// ---------------------------------------------------------------------------
#define PJ_AHI 0
#define PJ_ALO 16128
#define PJ_BHI 32256
#define PJ_BLO 41472
#define PJ_SMEM 50688

__global__ __launch_bounds__(256) void proj_kernel(
    const float* __restrict__ q, const float* __restrict__ k,
    const float* __restrict__ w_qs, const float* __restrict__ w_ks,
    const float* __restrict__ v)
{
    const int tid = threadIdx.x;

    // ---- z == 2: V^T frag-order image, one (kb,h) per (x,y) block
    if (blockIdx.z == 2) {
        const int bh = blockIdx.y * 8 + blockIdx.x;
        const float* vp = v + (size_t)(bh >> 3) * 51200 + (bh & 7) * 6400;
        uint32_t* VF = g_Vf + (size_t)bh * 3584;
        for (int e = tid; e < 3584; e += 256) {
            const int d = e / 56, p = e % 56;          // dv col, m-pair
            const int m0 = 2 * p, m1 = 2 * p + 1;
            float x0 = (m0 < LEN) ? vp[m0 * 64 + d] : 0.0f;
            float x1 = (m1 < LEN) ? vp[m1 * 64 + d] : 0.0f;
            __half2 hv = __floats2half2_rn(x0, x1);
            const int ks = p >> 3, uh = (p >> 2) & 1, t = p & 3;
            const int jv = d >> 3, g = d & 7;
            VF[((jv * 7) + ks) * 64 + (g * 4 + t) * 2 + uh] = *(uint32_t*)&hv;
        }
        return;
    }

    extern __shared__ char sm[];
    uint32_t* AHI = (uint32_t*)(sm + PJ_AHI);
    uint32_t* ALO = (uint32_t*)(sm + PJ_ALO);
    uint32_t* BHI = (uint32_t*)(sm + PJ_BHI);
    uint32_t* BLO = (uint32_t*)(sm + PJ_BLO);
    float* S = (float*)sm;

    const int cb = blockIdx.x, b = blockIdx.y, sel = blockIdx.z;
    const float* x = sel ? k : q;
    const float* w = sel ? w_ks : w_qs;

    const int warp = tid >> 5, lane = tid & 31;
    const int g = lane >> 2, t = lane & 3;

    float4 pa[7], pb[4];

    #pragma unroll
    for (int u = 0; u < 7; u++) {
        const int i = tid + 256 * u, r = i >> 4, c4 = i & 15;
        pa[u] = (r < LEN)
            ? *(const float4*)(x + (size_t)(b * 100 + r) * DMODEL + c4 * 4)
            : make_float4(0.f, 0.f, 0.f, 0.f);
    }
    #pragma unroll
    for (int u = 0; u < 4; u++) {
        const int i = tid + 256 * u, r = i >> 4, c4 = i & 15;
        pb[u] = *(const float4*)(w + (size_t)(cb * 64 + r) * DMODEL + c4 * 4);
    }

    float acc[7][4] = {};

    for (int c = 0; c < 8; c++) {
        __syncthreads();
        #pragma unroll
        for (int u = 0; u < 7; u++) {
            const int i = tid + 256 * u, r = i >> 4, c4 = i & 15;
            uint32_t h0, l0, h1, l1;
            split2h(pa[u].x, pa[u].y, h0, l0);
            split2h(pa[u].z, pa[u].w, h1, l1);
            AHI[r * 36 + c4 * 2] = h0; AHI[r * 36 + c4 * 2 + 1] = h1;
            ALO[r * 36 + c4 * 2] = l0; ALO[r * 36 + c4 * 2 + 1] = l1;
        }
        #pragma unroll
        for (int u = 0; u < 4; u++) {
            const int i = tid + 256 * u, r = i >> 4, c4 = i & 15;
            uint32_t h0, l0, h1, l1;
            split2h(pb[u].x, pb[u].y, h0, l0);
            split2h(pb[u].z, pb[u].w, h1, l1);
            BHI[r * 36 + c4 * 2] = h0; BHI[r * 36 + c4 * 2 + 1] = h1;
            BLO[r * 36 + c4 * 2] = l0; BLO[r * 36 + c4 * 2 + 1] = l1;
        }
        __syncthreads();
        if (c < 7) {
            const int k0 = (c + 1) * 64;
            #pragma unroll
            for (int u = 0; u < 7; u++) {
                const int i = tid + 256 * u, r = i >> 4, c4 = i & 15;
                pa[u] = (r < LEN)
                    ? *(const float4*)(x + (size_t)(b * 100 + r) * DMODEL + k0 + c4 * 4)
                    : make_float4(0.f, 0.f, 0.f, 0.f);
            }
            #pragma unroll
            for (int u = 0; u < 4; u++) {
                const int i = tid + 256 * u, r = i >> 4, c4 = i & 15;
                pb[u] = *(const float4*)(w + (size_t)(cb * 64 + r) * DMODEL + k0 + c4 * 4);
            }
        }
        #pragma unroll
        for (int ks = 0; ks < 4; ks++) {
            const int nb = (warp * 8 + g) * 36 + ks * 8 + t;
            const uint32_t bh0 = BHI[nb], bh1 = BHI[nb + 4];
            const uint32_t bl0 = BLO[nb], bl1 = BLO[nb + 4];
            #pragma unroll
            for (int i = 0; i < 7; i++) {
                const int rb = (i * 16 + g) * 36 + ks * 8 + t;
                const uint32_t ah0 = AHI[rb], ah1 = AHI[rb + 288];
                const uint32_t ah2 = AHI[rb + 4], ah3 = AHI[rb + 292];
                const uint32_t al0 = ALO[rb], al1 = ALO[rb + 288];
                const uint32_t al2 = ALO[rb + 4], al3 = ALO[rb + 292];
                mma_f16(acc[i], ah0, ah1, ah2, ah3, bh0, bh1);
                mma_f16(acc[i], ah0, ah1, ah2, ah3, bl0, bl1);
                mma_f16(acc[i], al0, al1, al2, al3, bh0, bh1);
            }
        }
    }
    __syncthreads();

    #pragma unroll
    for (int i = 0; i < 7; i++) {
        const int cc = warp * 8 + 2 * t;
        *(float2*)(S + (i * 16 + g) * 68 + cc)     = make_float2(acc[i][0], acc[i][1]);
        *(float2*)(S + (i * 16 + g + 8) * 68 + cc) = make_float2(acc[i][2], acc[i][3]);
    }
    __syncthreads();

    // normalize slab row tid (<100) = raw-view chunk n = tid*8 + cb.
    if (tid < LEN) {
        const float* Sr = S + tid * 68;
        float ss = 0.0f;
        #pragma unroll
        for (int u = 0; u < 16; u++) {
            float4 xv = *(const float4*)(Sr + u * 4);
            ss += xv.x * xv.x + xv.y * xv.y + xv.z * xv.z + xv.w * xv.w;
        }
        const float inv = 1.0f / fmaxf(sqrtf(ss), 1e-12f);
        const int n = tid * 8 + cb;
        const int hh = n / 100, ll = n % 100;
        if (sel == 0) {
            // Q: scatter into A frag-order image
            uint32_t* GH = g_Qh + (size_t)(b * 8 + hh) * 4096;
            uint32_t* GX = g_Qx + (size_t)(b * 8 + hh) * 4096;
            const int fsq = ll >> 4, rr = ll & 15;
            const int gbit = (rr >> 3) & 1, gg = rr & 7;
            #pragma unroll
            for (int w = 0; w < 32; w++) {
                float2 pv = *(const float2*)(Sr + 2 * w);
                uint32_t hw, xw;
                splitrx(pv.x * inv, pv.y * inv, hw, xw);
                const int ks = w >> 3, uh = (w >> 2) & 1, tt = w & 3;
                const int idx = (fsq * 4 + ks) * 128
                              + (gg * 4 + tt) * 4 + gbit + 2 * uh;
                GH[idx] = hw; GX[idx] = xw;
            }
        } else {
            // K: scatter into B frag-order image (col = ll)
            uint32_t* GH = g_Kh + (size_t)(b * 8 + hh) * 3584;
            uint32_t* GX = g_Kx + (size_t)(b * 8 + hh) * 3584;
            const int jj = ll >> 3, gg = ll & 7;
            #pragma unroll
            for (int w = 0; w < 32; w++) {
                float2 pv = *(const float2*)(Sr + 2 * w);
                uint32_t hw, xw;
                splitrx(pv.x * inv, pv.y * inv, hw, xw);
                const int ks = w >> 3, uh = (w >> 2) & 1, tt = w & 3;
                const int idx = (jj * 4 + ks) * 64 + (gg * 4 + tt) * 2 + uh;
                GH[idx] = hw; GX[idx] = xw;
            }
        }
    }
}

// ---------------------------------------------------------------------------
// Kernel 2: attention per (qb,kb,h), 8 warps — ZERO smem, ZERO barriers.
// Warp fs owns rows [fs*16, fs*16+16) x ALL 112 key cols.
//   S: 14 j strips x 4 ks x 2 mma; per-j epilogue packs P into registers
//      pp0/pp1[14] (thread (g,t) holds col word 4j+t for rows g, g+8 — which
//      IS the O-phase A-fragment layout: O ks uses j=2ks (word 8ks+t) and
//      j=2ks+1 (word 8ks+4+t)).
//   Rowsums: in-thread over j, then width-4 shuffle over t -> complete.
//   O: 7 ks x 8 jv strips, V frags via LDG.64 from frag image.
// ---------------------------------------------------------------------------
__global__ __launch_bounds__(256, 2) void attn_kernel(float* __restrict__ out)
{
    const int bx = blockIdx.x;
    const int h  = bx & 7;
    const int qb = (bx >> 3) & 31;
    const int kb = bx >> 8;
    const int tid = threadIdx.x;
    const int fs = tid >> 5, lane = tid & 31;
    const int g = lane >> 2, t = lane & 3;

    // ---- A-cache: direct coalesced LDG.128 from frag-order Q image
    uint32_t ah[4][4], ax[4][4];
    {
        const uint4* qh4 = (const uint4*)(g_Qh + (size_t)(qb * 8 + h) * 4096);
        const uint4* qx4 = (const uint4*)(g_Qx + (size_t)(qb * 8 + h) * 4096);
        #pragma unroll
        for (int ks = 0; ks < 4; ks++) {
            const int idx = (fs * 4 + ks) * 32 + lane;
            uint4 a = qh4[idx];
            ah[ks][0] = a.x; ah[ks][1] = a.y; ah[ks][2] = a.z; ah[ks][3] = a.w;
            uint4 b = qx4[idx];
            ax[ks][0] = b.x; ax[ks][1] = b.y; ax[ks][2] = b.z; ax[ks][3] = b.w;
        }
    }

    // ---- K frag pointers + preload j=0
    const uint2* KH2 = (const uint2*)(g_Kh + (size_t)(kb * 8 + h) * 3584);
    const uint2* KX2 = (const uint2*)(g_Kx + (size_t)(kb * 8 + h) * 3584);
    uint2 bh[4], bxv[4];
    #pragma unroll
    for (int ks = 0; ks < 4; ks++) {
        bh[ks]  = KH2[ks * 32 + lane];
        bxv[ks] = KX2[ks * 32 + lane];
    }

    // ---- S phase over all 14 j strips; P stays in registers
    uint32_t pp0[14], pp1[14];
    float rs0 = 0.f, rs1 = 0.f;
    #pragma unroll
    for (int j = 0; j < 14; j++) {
        uint2 nh[4], nx[4];
        if (j < 13) {
            #pragma unroll
            for (int ks = 0; ks < 4; ks++) {
                nh[ks] = KH2[((j + 1) * 4 + ks) * 32 + lane];
                nx[ks] = KX2[((j + 1) * 4 + ks) * 32 + lane];
            }
        }
        float shh[4] = {}, sxy[4] = {};
        #pragma unroll
        for (int ks = 0; ks < 4; ks++) {
            mma_f16(shh, ah[ks][0], ah[ks][1], ah[ks][2], ah[ks][3],
                    bh[ks].x, bh[ks].y);
            mma_f16(sxy, ax[ks][0], ax[ks][1], ax[ks][2], ax[ks][3],
                    bxv[ks].x, bxv[ks].y);
        }
        const int col = 8 * j + 2 * t;
        float e[4];
        #pragma unroll
        for (int u = 0; u < 4; u++) {
            const float sf = fmaf(sxy[u] - shh[u], RINV, shh[u]);
            e[u] = __expf(fmaf(TEMP, fmaxf(sf, 0.0f), -LN8192));
        }
        if (col >= LEN)     { e[0] = 0.f; e[2] = 0.f; }
        if (col + 1 >= LEN) { e[1] = 0.f; e[3] = 0.f; }
        rs0 += e[0] + e[1];
        rs1 += e[2] + e[3];
        __half2 h01 = __floats2half2_rn(e[0], e[1]);
        __half2 h23 = __floats2half2_rn(e[2], e[3]);
        pp0[j] = *(uint32_t*)&h01;
        pp1[j] = *(uint32_t*)&h23;
        if (j < 13) {
            #pragma unroll
            for (int ks = 0; ks < 4; ks++) { bh[ks] = nh[ks]; bxv[ks] = nx[ks]; }
        }
    }
    // complete rowsums within the 4-lane t-group (cols {2t,2t+1} mod 8 x 14 j)
    rs0 += __shfl_xor_sync(0xffffffffu, rs0, 1);
    rs0 += __shfl_xor_sync(0xffffffffu, rs0, 2);
    rs1 += __shfl_xor_sync(0xffffffffu, rs1, 1);
    rs1 += __shfl_xor_sync(0xffffffffu, rs1, 2);

    // ---- O phase: rows [fs*16,+16) x all 64 dv cols, K=112, 1-term V
    const uint2* vf2 = (const uint2*)(g_Vf + (size_t)(kb * 8 + h) * 3584);
    float o[8][4] = {};
    #pragma unroll
    for (int ks = 0; ks < 7; ks++) {
        const uint32_t a0 = pp0[2 * ks],     a1 = pp1[2 * ks];
        const uint32_t a2 = pp0[2 * ks + 1], a3 = pp1[2 * ks + 1];
        #pragma unroll
        for (int jv = 0; jv < 8; jv++) {
            const uint2 bv = vf2[(jv * 7 + ks) * 32 + lane];
            mma_f16(o[jv], a0, a1, a2, a3, bv.x, bv.y);
        }
    }

    // ---- output: divide by rowsum, write [kb][qb][l][h*64+d]
    const size_t ob = (size_t)(kb * 32 + qb) * LEN * DMODEL + h * 64;
    const int r = fs * 16 + g;
    const float inv0 = 1.0f / rs0;
    const float inv1 = 1.0f / rs1;
    #pragma unroll
    for (int jv = 0; jv < 8; jv++) {
        const int cc = jv * 8 + 2 * t;
        if (r < LEN) {
            *(float2*)(out + ob + (size_t)r * DMODEL + cc) =
                make_float2(o[jv][0] * inv0, o[jv][1] * inv0);
        }
        if (r + 8 < LEN) {
            *(float2*)(out + ob + (size_t)(r + 8) * DMODEL + cc) =
                make_float2(o[jv][2] * inv1, o[jv][3] * inv1);
        }
    }
}

// ---------------------------------------------------------------------------
extern "C" void kernel_launch(void* const* d_in, const int* in_sizes, int n_in,
                              void* d_out, int out_size)
{
    const float* q    = (const float*)d_in[0];
    const float* k    = (const float*)d_in[1];
    const float* v    = (const float*)d_in[2];
    const float* w_qs = (const float*)d_in[3];
    const float* w_ks = (const float*)d_in[4];
    float* out = (float*)d_out;

    cudaFuncSetAttribute(proj_kernel,
                         cudaFuncAttributeMaxDynamicSharedMemorySize, PJ_SMEM);

    proj_kernel<<<dim3(8, 32, 3), 256, PJ_SMEM>>>(q, k, w_qs, w_ks, v);
    attn_kernel<<<8192, 256>>>(out);
}

// round 17
// speedup vs baseline: 1.1760x; 1.1760x over previous
#include <cuda_runtime.h>
#include <cuda_fp16.h>
#include <cstdint>

// Problem constants
#define NHEAD   8
#define DK      64
#define LEN     100
#define BS      32
#define DMODEL  512
#define TEMP    20.0f
#define LN8192  9.0109133f
#define RSCALE  32.0f          // residual scale for 2-mma exact-ish S
#define RINV    0.03125f       // 1/32

// Q: FRAGMENT-ORDER image per (b,h): word idx = (fs*4+ks)*128 + lane*4+u,
//    fs = row/16 (0..7). Unwritten words (rows>=100) stay zero (static init).
__device__ __align__(16) uint32_t g_Qh[BS * NHEAD * 4096];
__device__ __align__(16) uint32_t g_Qx[BS * NHEAD * 4096];
// K: COMBINED frag-order B image per (b,h): uint4 at [(j*4+ks)*32 + lane] =
//    (bh0, bh1, bx0, bx1) for fragment (j,ks), lane = 4g+t.
//    Cols >= 100 stay zero (static init).
__device__ uint4 g_Kc[BS * NHEAD * 1792];
// V: FRAGMENT-ORDER image per (kb,h): word idx = ((jv*7)+ks)*64 + lane*2 + u.
__device__ __align__(16) uint32_t g_Vf[BS * NHEAD * 3584];

// ---------------------------------------------------------------------------
__device__ __forceinline__ void mma_f16(float c[4],
    uint32_t a0, uint32_t a1, uint32_t a2, uint32_t a3,
    uint32_t b0, uint32_t b1)
{
    asm volatile(
        "mma.sync.aligned.m16n8k16.row.col.f32.f16.f16.f32 "
        "{%0,%1,%2,%3}, {%4,%5,%6,%7}, {%8,%9}, {%0,%1,%2,%3};"
        : "+f"(c[0]), "+f"(c[1]), "+f"(c[2]), "+f"(c[3])
        : "r"(a0), "r"(a1), "r"(a2), "r"(a3), "r"(b0), "r"(b1));
}

__device__ __forceinline__ void split2h(float x0, float x1,
                                        uint32_t& hi, uint32_t& lo)
{
    __half2 h = __floats2half2_rn(x0, x1);
    float2 hf = __half22float2(h);
    __half2 l = __floats2half2_rn(x0 - hf.x, x1 - hf.y);
    hi = *(uint32_t*)&h;
    lo = *(uint32_t*)&l;
}

// h = fp16(y), x = fp16(h + 32*(y-h))  (scaled-residual pair)
__device__ __forceinline__ void splitrx(float y0, float y1,
                                        uint32_t& hw, uint32_t& xw)
{
    __half2 h = __floats2half2_rn(y0, y1);
    float2 hf = __half22float2(h);
    __half2 x = __floats2half2_rn(fmaf(RSCALE, y0 - hf.x, hf.x),
                                  fmaf(RSCALE, y1 - hf.y, hf.y));
    hw = *(uint32_t*)&h;
    xw = *(uint32_t*)&x;
}

// ---------------------------------------------------------------------------
// Kernel 1: projection (z=0: Q frag-order; z=1: K combined frag image) +
//           z=2 slice: V^T frag-order image builder.
// ---------------------------------------------------------------------------
#define PJ_AHI 0
#define PJ_ALO 16128
#define PJ_BHI 32256
#define PJ_BLO 41472
#define PJ_SMEM 50688

__global__ __launch_bounds__(256) void proj_kernel(
    const float* __restrict__ q, const float* __restrict__ k,
    const float* __restrict__ w_qs, const float* __restrict__ w_ks,
    const float* __restrict__ v)
{
    const int tid = threadIdx.x;

    // ---- z == 2: V^T frag-order image, one (kb,h) per (x,y) block
    if (blockIdx.z == 2) {
        const int bh = blockIdx.y * 8 + blockIdx.x;
        const float* vp = v + (size_t)(bh >> 3) * 51200 + (bh & 7) * 6400;
        uint32_t* VF = g_Vf + (size_t)bh * 3584;
        for (int e = tid; e < 3584; e += 256) {
            const int d = e / 56, p = e % 56;          // dv col, m-pair
            const int m0 = 2 * p, m1 = 2 * p + 1;
            float x0 = (m0 < LEN) ? vp[m0 * 64 + d] : 0.0f;
            float x1 = (m1 < LEN) ? vp[m1 * 64 + d] : 0.0f;
            __half2 hv = __floats2half2_rn(x0, x1);
            const int ks = p >> 3, uh = (p >> 2) & 1, t = p & 3;
            const int jv = d >> 3, g = d & 7;
            VF[((jv * 7) + ks) * 64 + (g * 4 + t) * 2 + uh] = *(uint32_t*)&hv;
        }
        return;
    }

    extern __shared__ char sm[];
    uint32_t* AHI = (uint32_t*)(sm + PJ_AHI);
    uint32_t* ALO = (uint32_t*)(sm + PJ_ALO);
    uint32_t* BHI = (uint32_t*)(sm + PJ_BHI);
    uint32_t* BLO = (uint32_t*)(sm + PJ_BLO);
    float* S = (float*)sm;

    const int cb = blockIdx.x, b = blockIdx.y, sel = blockIdx.z;
    const float* x = sel ? k : q;
    const float* w = sel ? w_ks : w_qs;

    const int warp = tid >> 5, lane = tid & 31;
    const int g = lane >> 2, t = lane & 3;

    float4 pa[7], pb[4];

    #pragma unroll
    for (int u = 0; u < 7; u++) {
        const int i = tid + 256 * u, r = i >> 4, c4 = i & 15;
        pa[u] = (r < LEN)
            ? *(const float4*)(x + (size_t)(b * 100 + r) * DMODEL + c4 * 4)
            : make_float4(0.f, 0.f, 0.f, 0.f);
    }
    #pragma unroll
    for (int u = 0; u < 4; u++) {
        const int i = tid + 256 * u, r = i >> 4, c4 = i & 15;
        pb[u] = *(const float4*)(w + (size_t)(cb * 64 + r) * DMODEL + c4 * 4);
    }

    float acc[7][4] = {};

    for (int c = 0; c < 8; c++) {
        __syncthreads();
        #pragma unroll
        for (int u = 0; u < 7; u++) {
            const int i = tid + 256 * u, r = i >> 4, c4 = i & 15;
            uint32_t h0, l0, h1, l1;
            split2h(pa[u].x, pa[u].y, h0, l0);
            split2h(pa[u].z, pa[u].w, h1, l1);
            AHI[r * 36 + c4 * 2] = h0; AHI[r * 36 + c4 * 2 + 1] = h1;
            ALO[r * 36 + c4 * 2] = l0; ALO[r * 36 + c4 * 2 + 1] = l1;
        }
        #pragma unroll
        for (int u = 0; u < 4; u++) {
            const int i = tid + 256 * u, r = i >> 4, c4 = i & 15;
            uint32_t h0, l0, h1, l1;
            split2h(pb[u].x, pb[u].y, h0, l0);
            split2h(pb[u].z, pb[u].w, h1, l1);
            BHI[r * 36 + c4 * 2] = h0; BHI[r * 36 + c4 * 2 + 1] = h1;
            BLO[r * 36 + c4 * 2] = l0; BLO[r * 36 + c4 * 2 + 1] = l1;
        }
        __syncthreads();
        if (c < 7) {
            const int k0 = (c + 1) * 64;
            #pragma unroll
            for (int u = 0; u < 7; u++) {
                const int i = tid + 256 * u, r = i >> 4, c4 = i & 15;
                pa[u] = (r < LEN)
                    ? *(const float4*)(x + (size_t)(b * 100 + r) * DMODEL + k0 + c4 * 4)
                    : make_float4(0.f, 0.f, 0.f, 0.f);
            }
            #pragma unroll
            for (int u = 0; u < 4; u++) {
                const int i = tid + 256 * u, r = i >> 4, c4 = i & 15;
                pb[u] = *(const float4*)(w + (size_t)(cb * 64 + r) * DMODEL + k0 + c4 * 4);
            }
        }
        #pragma unroll
        for (int ks = 0; ks < 4; ks++) {
            const int nb = (warp * 8 + g) * 36 + ks * 8 + t;
            const uint32_t bh0 = BHI[nb], bh1 = BHI[nb + 4];
            const uint32_t bl0 = BLO[nb], bl1 = BLO[nb + 4];
            #pragma unroll
            for (int i = 0; i < 7; i++) {
                const int rb = (i * 16 + g) * 36 + ks * 8 + t;
                const uint32_t ah0 = AHI[rb], ah1 = AHI[rb + 288];
                const uint32_t ah2 = AHI[rb + 4], ah3 = AHI[rb + 292];
                const uint32_t al0 = ALO[rb], al1 = ALO[rb + 288];
                const uint32_t al2 = ALO[rb + 4], al3 = ALO[rb + 292];
                mma_f16(acc[i], ah0, ah1, ah2, ah3, bh0, bh1);
                mma_f16(acc[i], ah0, ah1, ah2, ah3, bl0, bl1);
                mma_f16(acc[i], al0, al1, al2, al3, bh0, bh1);
            }
        }
    }
    __syncthreads();

    #pragma unroll
    for (int i = 0; i < 7; i++) {
        const int cc = warp * 8 + 2 * t;
        *(float2*)(S + (i * 16 + g) * 68 + cc)     = make_float2(acc[i][0], acc[i][1]);
        *(float2*)(S + (i * 16 + g + 8) * 68 + cc) = make_float2(acc[i][2], acc[i][3]);
    }
    __syncthreads();

    // normalize slab row tid (<100) = raw-view chunk n = tid*8 + cb.
    if (tid < LEN) {
        const float* Sr = S + tid * 68;
        float ss = 0.0f;
        #pragma unroll
        for (int u = 0; u < 16; u++) {
            float4 xv = *(const float4*)(Sr + u * 4);
            ss += xv.x * xv.x + xv.y * xv.y + xv.z * xv.z + xv.w * xv.w;
        }
        const float inv = 1.0f / fmaxf(sqrtf(ss), 1e-12f);
        const int n = tid * 8 + cb;
        const int hh = n / 100, ll = n % 100;
        if (sel == 0) {
            // Q: scatter into A frag-order image
            uint32_t* GH = g_Qh + (size_t)(b * 8 + hh) * 4096;
            uint32_t* GX = g_Qx + (size_t)(b * 8 + hh) * 4096;
            const int fsq = ll >> 4, rr = ll & 15;
            const int gbit = (rr >> 3) & 1, gg = rr & 7;
            #pragma unroll
            for (int w = 0; w < 32; w++) {
                float2 pv = *(const float2*)(Sr + 2 * w);
                uint32_t hw, xw;
                splitrx(pv.x * inv, pv.y * inv, hw, xw);
                const int ks = w >> 3, uh = (w >> 2) & 1, tt = w & 3;
                const int idx = (fsq * 4 + ks) * 128
                              + (gg * 4 + tt) * 4 + gbit + 2 * uh;
                GH[idx] = hw; GX[idx] = xw;
            }
        } else {
            // K: combined frag image, one uint4 per (ks,tt)
            uint4* GC = g_Kc + (size_t)(b * 8 + hh) * 1792;
            const int jj = ll >> 3, gg = ll & 7;
            #pragma unroll
            for (int ks = 0; ks < 4; ks++) {
                #pragma unroll
                for (int tt = 0; tt < 4; tt++) {
                    const int w0 = ks * 8 + tt, w1 = w0 + 4;
                    float2 p0 = *(const float2*)(Sr + 2 * w0);
                    float2 p1 = *(const float2*)(Sr + 2 * w1);
                    uint32_t h0, x0, h1, x1;
                    splitrx(p0.x * inv, p0.y * inv, h0, x0);
                    splitrx(p1.x * inv, p1.y * inv, h1, x1);
                    GC[(jj * 4 + ks) * 32 + gg * 4 + tt] =
                        make_uint4(h0, h1, x0, x1);
                }
            }
        }
    }
}

// ---------------------------------------------------------------------------
// Kernel 2: attention per (qb,kb,h), 8 warps, M=128 (round-12 structure).
//   A-cache: LDG.128 from Q frag image. K staged as combined frag image:
//   one LDS.128 per (j,ks) gives all four B words. P stored frag-order in
//   two smem arrays (even/odd j): STS.64 epilogue, LDS.64 O-phase.
//   S->O sync: 64-thread NAMED barrier per wm pair (warps wm, wm+4).
// ---------------------------------------------------------------------------
#define OFF_RS   0                        // 128 rows x 2 floats = 1024B
#define OFF_P0   1024                     // 8 ib x 7 ks x 64 w = 14336B
#define OFF_P1   (OFF_P0 + 14336)         // 15360
#define OFF_KC   (OFF_P1 + 14336)         // 29696: 1792 uint4 = 28672B
#define ATTN_SMEM (OFF_KC + 28672)        // 58368 -> 2 CTAs/SM

__global__ __launch_bounds__(256, 2) void attn_kernel(float* __restrict__ out)
{
    extern __shared__ char sm[];
    float* RS = (float*)(sm + OFF_RS);
    uint32_t* P0 = (uint32_t*)(sm + OFF_P0);
    uint32_t* P1 = (uint32_t*)(sm + OFF_P1);
    uint4* KC = (uint4*)(sm + OFF_KC);

    const int bx = blockIdx.x;
    const int h  = bx & 7;
    const int qb = (bx >> 3) & 31;
    const int kb = bx >> 8;
    const int tid = threadIdx.x;
    const int warp = tid >> 5, lane = tid & 31;
    const int g = lane >> 2, t = lane & 3;
    const int wm = warp & 3, wn = warp >> 2;
    const int r0 = wm * 32;
    const int c0 = wn * 56;

    // ---- A-cache: direct coalesced LDG.128 from frag-order Q image
    uint32_t ah[2][4][4], ax[2][4][4];
    {
        const uint4* qh4 = (const uint4*)(g_Qh + (size_t)(qb * 8 + h) * 4096);
        const uint4* qx4 = (const uint4*)(g_Qx + (size_t)(qb * 8 + h) * 4096);
        #pragma unroll
        for (int i = 0; i < 2; i++) {
            #pragma unroll
            for (int ks = 0; ks < 4; ks++) {
                const int idx = ((wm * 2 + i) * 4 + ks) * 32 + lane;
                uint4 a = qh4[idx];
                ah[i][ks][0] = a.x; ah[i][ks][1] = a.y;
                ah[i][ks][2] = a.z; ah[i][ks][3] = a.w;
                uint4 b = qx4[idx];
                ax[i][ks][0] = b.x; ax[i][ks][1] = b.y;
                ax[i][ks][2] = b.z; ax[i][ks][3] = b.w;
            }
        }
    }

    // ---- K staging: straight coalesced uint4 copy of combined frag image
    {
        const uint4* skc = g_Kc + (size_t)(kb * 8 + h) * 1792;
        for (int i = tid; i < 1792; i += 256) KC[i] = skc[i];
    }
    __syncthreads();

    // ---- S phase with per-j fused epilogue
    float rs[2][2] = {{0.f, 0.f}, {0.f, 0.f}};
    #pragma unroll
    for (int j = 0; j < 7; j++) {
        const int jg = wn * 7 + j;                // global j strip
        uint4 kc[4];
        #pragma unroll
        for (int ks = 0; ks < 4; ks++)
            kc[ks] = KC[(jg * 4 + ks) * 32 + lane];   // LDS.128

        float shh[2][4] = {}, sxy[2][4] = {};
        #pragma unroll
        for (int ks = 0; ks < 4; ks++) {
            #pragma unroll
            for (int i = 0; i < 2; i++) {
                mma_f16(shh[i], ah[i][ks][0], ah[i][ks][1], ah[i][ks][2], ah[i][ks][3],
                        kc[ks].x, kc[ks].y);
                mma_f16(sxy[i], ax[i][ks][0], ax[i][ks][1], ax[i][ks][2], ax[i][ks][3],
                        kc[ks].z, kc[ks].w);
            }
        }
        const int col = c0 + 8 * j + 2 * t;
        const int oks = jg >> 1;
        uint32_t* PP = (jg & 1) ? P1 : P0;
        #pragma unroll
        for (int i = 0; i < 2; i++) {
            float e[4];
            #pragma unroll
            for (int u = 0; u < 4; u++) {
                const float sf = fmaf(sxy[i][u] - shh[i][u], RINV, shh[i][u]);
                e[u] = __expf(fmaf(TEMP, fmaxf(sf, 0.0f), -LN8192));
            }
            if (col >= LEN)     { e[0] = 0.f; e[2] = 0.f; }
            if (col + 1 >= LEN) { e[1] = 0.f; e[3] = 0.f; }
            rs[i][0] += e[0] + e[1];
            rs[i][1] += e[2] + e[3];
            __half2 h01 = __floats2half2_rn(e[0], e[1]);
            __half2 h23 = __floats2half2_rn(e[2], e[3]);
            // frag-order P: (row g word, row g+8 word) as one STS.64
            const int base = ((wm * 2 + i) * 7 + oks) * 64 + lane * 2;
            *(uint2*)&PP[base] = make_uint2(*(uint32_t*)&h01, *(uint32_t*)&h23);
        }
    }
    // rowsum reduction (width-4 k-group shuffle), 2 partials per row
    #pragma unroll
    for (int i = 0; i < 2; i++) {
        rs[i][0] += __shfl_xor_sync(0xffffffffu, rs[i][0], 1);
        rs[i][0] += __shfl_xor_sync(0xffffffffu, rs[i][0], 2);
        rs[i][1] += __shfl_xor_sync(0xffffffffu, rs[i][1], 1);
        rs[i][1] += __shfl_xor_sync(0xffffffffu, rs[i][1], 2);
        if (t == 0) {
            RS[(r0 + 16 * i + g) * 2 + wn]     = rs[i][0];
            RS[(r0 + 16 * i + g + 8) * 2 + wn] = rs[i][1];
        }
    }

    // ---- named barrier: only the wm pair (warps wm, wm+4) must meet
    asm volatile("bar.sync %0, %1;" :: "r"(wm + 1), "r"(64) : "memory");

    // ---- O phase: warp rows [r0,r0+32) x dv cols [wn*32,+32), K=112, 1-term
    const uint2* vf2 = (const uint2*)(g_Vf + (size_t)(kb * 8 + h) * 3584);
    float o[2][4][4] = {};
    #pragma unroll
    for (int oks = 0; oks < 7; oks++) {
        uint32_t a[2][4];
        #pragma unroll
        for (int i = 0; i < 2; i++) {
            const int base = ((wm * 2 + i) * 7 + oks) * 64 + lane * 2;
            uint2 p0v = *(const uint2*)&P0[base];   // (a0, a1)
            uint2 p1v = *(const uint2*)&P1[base];   // (a2, a3)
            a[i][0] = p0v.x; a[i][1] = p0v.y;
            a[i][2] = p1v.x; a[i][3] = p1v.y;
        }
        #pragma unroll
        for (int jv = 0; jv < 4; jv++) {
            const uint2 bv = vf2[((wn * 4 + jv) * 7 + oks) * 32 + lane];
            #pragma unroll
            for (int i = 0; i < 2; i++) {
                mma_f16(o[i][jv], a[i][0], a[i][1], a[i][2], a[i][3], bv.x, bv.y);
            }
        }
    }

    // ---- output: divide by rowsum, write [kb][qb][l][h*64+d]
    const size_t ob = (size_t)(kb * 32 + qb) * LEN * DMODEL + h * 64;
    #pragma unroll
    for (int i = 0; i < 2; i++) {
        const int r = r0 + 16 * i + g;
        float inv0 = 0.f, inv1 = 0.f;
        if (r < LEN)     inv0 = 1.0f / (RS[r * 2] + RS[r * 2 + 1]);
        if (r + 8 < LEN) inv1 = 1.0f / (RS[(r + 8) * 2] + RS[(r + 8) * 2 + 1]);
        #pragma unroll
        for (int jv = 0; jv < 4; jv++) {
            const int cc = wn * 32 + 8 * jv + 2 * t;
            if (r < LEN) {
                *(float2*)(out + ob + (size_t)r * DMODEL + cc) =
                    make_float2(o[i][jv][0] * inv0, o[i][jv][1] * inv0);
            }
            if (r + 8 < LEN) {
                *(float2*)(out + ob + (size_t)(r + 8) * DMODEL + cc) =
                    make_float2(o[i][jv][2] * inv1, o[i][jv][3] * inv1);
            }
        }
    }
}

// ---------------------------------------------------------------------------
extern "C" void kernel_launch(void* const* d_in, const int* in_sizes, int n_in,
                              void* d_out, int out_size)
{
    const float* q    = (const float*)d_in[0];
    const float* k    = (const float*)d_in[1];
    const float* v    = (const float*)d_in[2];
    const float* w_qs = (const float*)d_in[3];
    const float* w_ks = (const float*)d_in[4];
    float* out = (float*)d_out;

    cudaFuncSetAttribute(proj_kernel,
                         cudaFuncAttributeMaxDynamicSharedMemorySize, PJ_SMEM);
    cudaFuncSetAttribute(attn_kernel,
                         cudaFuncAttributeMaxDynamicSharedMemorySize, ATTN_SMEM);

    proj_kernel<<<dim3(8, 32, 3), 256, PJ_SMEM>>>(q, k, w_qs, w_ks, v);
    attn_kernel<<<8192, 256, ATTN_SMEM>>>(out);
}